// round 15
// baseline (speedup 1.0000x reference)
#include <cuda_runtime.h>

namespace {
constexpr int B_ = 512, M_ = 8, S_ = 4, K_ = 64, TH_ = 16, Z_ = 16, H_ = 16;
constexpr float LOG2PI = 1.8378770664093453f;
}

// Energy for CNT compacted m-rows sharing one software-pipelined weight pass.
// zp lives in the caller's padded shared row (conflict-free, per-thread).
template <int CNT>
__device__ __forceinline__ float energy_group(
    int base, const float* __restrict__ zp_sh,   // this thread's zp row (shared)
    const float (*__restrict__ tpart)[16],
    const float (*__restrict__ e2w)[16],
    const float* __restrict__ e2b,
    const float* __restrict__ e3w)
{
    float h1[CNT][16];
#pragma unroll
    for (int i = 0; i < CNT; i++) {
        const float4* tp = (const float4*)tpart[base + i];
#pragma unroll
        for (int q = 0; q < 4; q++) {
            float4 t = tp[q];
            h1[i][4*q+0] = fmaxf(t.x + zp_sh[4*q+0], 0.f);
            h1[i][4*q+1] = fmaxf(t.y + zp_sh[4*q+1], 0.f);
            h1[i][4*q+2] = fmaxf(t.z + zp_sh[4*q+2], 0.f);
            h1[i][4*q+3] = fmaxf(t.w + zp_sh[4*q+3], 0.f);
        }
    }
    float energy = 0.f;
    // software pipeline: weights for g+1 loaded during g's FMAs
    const float4* wr = (const float4*)e2w[0];
    float4 w0 = wr[0], w1 = wr[1], w2 = wr[2], w3v = wr[3];
    float bias = e2b[0], w3e = e3w[0];
#pragma unroll 1
    for (int g = 0; g < 15; g++) {
        const float4* wrn = (const float4*)e2w[g + 1];
        float4 nw0 = wrn[0], nw1 = wrn[1], nw2 = wrn[2], nw3 = wrn[3];
        float nbias = e2b[g + 1], nw3e = e3w[g + 1];

        float acc[CNT];
#pragma unroll
        for (int i = 0; i < CNT; i++) acc[i] = bias;
#pragma unroll
        for (int i = 0; i < CNT; i++) {
            acc[i] = fmaf(w0.x, h1[i][0],  acc[i]);
            acc[i] = fmaf(w0.y, h1[i][1],  acc[i]);
            acc[i] = fmaf(w0.z, h1[i][2],  acc[i]);
            acc[i] = fmaf(w0.w, h1[i][3],  acc[i]);
            acc[i] = fmaf(w1.x, h1[i][4],  acc[i]);
            acc[i] = fmaf(w1.y, h1[i][5],  acc[i]);
            acc[i] = fmaf(w1.z, h1[i][6],  acc[i]);
            acc[i] = fmaf(w1.w, h1[i][7],  acc[i]);
            acc[i] = fmaf(w2.x, h1[i][8],  acc[i]);
            acc[i] = fmaf(w2.y, h1[i][9],  acc[i]);
            acc[i] = fmaf(w2.z, h1[i][10], acc[i]);
            acc[i] = fmaf(w2.w, h1[i][11], acc[i]);
            acc[i] = fmaf(w3v.x, h1[i][12], acc[i]);
            acc[i] = fmaf(w3v.y, h1[i][13], acc[i]);
            acc[i] = fmaf(w3v.z, h1[i][14], acc[i]);
            acc[i] = fmaf(w3v.w, h1[i][15], acc[i]);
        }
        float rsum = fmaxf(acc[0], 0.f);
#pragma unroll
        for (int i = 1; i < CNT; i++) rsum += fmaxf(acc[i], 0.f);
        energy = fmaf(w3e, rsum, energy);

        w0 = nw0; w1 = nw1; w2 = nw2; w3v = nw3; bias = nbias; w3e = nw3e;
    }
    {   // peeled last iteration (g = 15)
        float acc[CNT];
#pragma unroll
        for (int i = 0; i < CNT; i++) acc[i] = bias;
#pragma unroll
        for (int i = 0; i < CNT; i++) {
            acc[i] = fmaf(w0.x, h1[i][0],  acc[i]);
            acc[i] = fmaf(w0.y, h1[i][1],  acc[i]);
            acc[i] = fmaf(w0.z, h1[i][2],  acc[i]);
            acc[i] = fmaf(w0.w, h1[i][3],  acc[i]);
            acc[i] = fmaf(w1.x, h1[i][4],  acc[i]);
            acc[i] = fmaf(w1.y, h1[i][5],  acc[i]);
            acc[i] = fmaf(w1.z, h1[i][6],  acc[i]);
            acc[i] = fmaf(w1.w, h1[i][7],  acc[i]);
            acc[i] = fmaf(w2.x, h1[i][8],  acc[i]);
            acc[i] = fmaf(w2.y, h1[i][9],  acc[i]);
            acc[i] = fmaf(w2.z, h1[i][10], acc[i]);
            acc[i] = fmaf(w2.w, h1[i][11], acc[i]);
            acc[i] = fmaf(w3v.x, h1[i][12], acc[i]);
            acc[i] = fmaf(w3v.y, h1[i][13], acc[i]);
            acc[i] = fmaf(w3v.z, h1[i][14], acc[i]);
            acc[i] = fmaf(w3v.w, h1[i][15], acc[i]);
        }
        float rsum = fmaxf(acc[0], 0.f);
#pragma unroll
        for (int i = 1; i < CNT; i++) rsum += fmaxf(acc[i], 0.f);
        energy = fmaf(w3e, rsum, energy);
    }
    return energy;
}

__device__ __forceinline__ float energy_dispatch(
    int base, int cnt, const float* zp_sh,
    const float (*tpart)[16], const float (*e2w)[16],
    const float* e2b, const float* e3w)
{
    switch (cnt) {
        case 1: return energy_group<1>(base, zp_sh, tpart, e2w, e2b, e3w);
        case 2: return energy_group<2>(base, zp_sh, tpart, e2w, e2b, e3w);
        case 3: return energy_group<3>(base, zp_sh, tpart, e2w, e2b, e3w);
        default: return energy_group<4>(base, zp_sh, tpart, e2w, e2b, e3w);
    }
}

__global__ void __launch_bounds__(256, 2) ebm_kernel(
    const float* __restrict__ thetas,
    const void*  __restrict__ nan_mask,
    const float* __restrict__ eps,
    const float* __restrict__ gumbel,
    const float* __restrict__ pi1_w,   const float* __restrict__ pi1_b,
    const float* __restrict__ pimu_w,  const float* __restrict__ pimu_b,
    const float* __restrict__ piprec_w,const float* __restrict__ piprec_b,
    const float* __restrict__ e1_w,    const float* __restrict__ e1_b,
    const float* __restrict__ e2_w,    const float* __restrict__ e2_b,
    const float* __restrict__ e3_w,    const float* __restrict__ e3_b,
    float* __restrict__ out)
{
    const int b = blockIdx.x;
    const int tid = threadIdx.x;

    __shared__ __align__(16) float sh_theta[M_][TH_];
    __shared__ __align__(16) float sh_e1w[H_][TH_ + Z_];   // [h][0:16]=W_t, [h][16:32]=W_z
    __shared__ __align__(16) float sh_e2w[H_][H_];
    __shared__ __align__(16) float sh_tpart[M_][H_];       // compacted valid m
    __shared__ float sh_zp[256][17];                       // per-thread zp, padded
    __shared__ float sh_e1b[H_], sh_e2b[H_], sh_e3w[H_];
    __shared__ float sh_mu[Z_], sh_std[Z_];
    __shared__ float sh_tsum[TH_], sh_h[H_];
    __shared__ float sh_logstd_sum, sh_e3b0;
    __shared__ int   sh_mv, sh_midx[M_];
    __shared__ float sh_logits[S_ * K_], sh_logiw[S_ * K_], sh_energy[S_ * K_];

    // ---- cooperative loads ----
    if (tid < 128) ((float*)sh_theta)[tid] = thetas[b * 128 + tid];
    ((float*)sh_e1w)[tid]       = e1_w[tid];
    ((float*)sh_e1w)[tid + 256] = e1_w[tid + 256];
    ((float*)sh_e2w)[tid]       = e2_w[tid];
    if (tid < 16) {
        sh_e1b[tid] = e1_b[tid];
        sh_e2b[tid] = e2_b[tid];
        sh_e3w[tid] = e3_w[tid];
    }
    if (tid == 16) sh_e3b0 = e3_b[0];

    // ---- inline mask-dtype detection (reads only the 4096 guaranteed bytes) ----
    unsigned int myf = 0;
    {
        const uint4* w4 = (const uint4*)nan_mask;
        uint4 v = __ldg(&w4[tid]);
        unsigned int xs[4] = {v.x, v.y, v.z, v.w};
#pragma unroll
        for (int q = 0; q < 4; q++) {
            unsigned int x = xs[q];
            if (x != 0u && x != 0x3F800000u) myf |= 1u;
            if (x == 0x3F800000u) myf |= 2u;
            if (x & 0xFFFFFF00u) myf |= 4u;
        }
    }
    const unsigned int flags = (unsigned int)__syncthreads_or((int)myf);
    const int mode = (!(flags & 1u) && (flags & 2u)) ? 2 : ((flags & 4u) ? 1 : 0);

    // ---- per-b head prep ----
    if (tid < 16) {
        float s = 0.f;
#pragma unroll
        for (int m = 0; m < M_; m++) s += sh_theta[m][tid];
        sh_tsum[tid] = s;
    }
    if (tid == 17) {
        int mv = 0;
#pragma unroll
        for (int m = 0; m < M_; m++) {
            bool masked;
            if (mode == 1)      masked = ((const unsigned char*)nan_mask)[b * M_ + m] != 0;
            else if (mode == 2) masked = ((const float*)nan_mask)[b * M_ + m] != 0.f;
            else                masked = ((const int*)nan_mask)[b * M_ + m] != 0;
            if (!masked) sh_midx[mv++] = m;
        }
        sh_mv = mv;
    }
    __syncthreads();
    if (tid < 16) {
        float a = __ldg(&pi1_b[tid]);
#pragma unroll
        for (int t = 0; t < 16; t++) a = fmaf(__ldg(&pi1_w[tid * 16 + t]), sh_tsum[t], a);
        sh_h[tid] = fmaxf(a, 0.f);
    }
    __syncthreads();
    if (tid < 16) {
        float mu = __ldg(&pimu_b[tid]), lp = __ldg(&piprec_b[tid]);
#pragma unroll
        for (int j = 0; j < 16; j++) {
            float hj = sh_h[j];
            mu = fmaf(__ldg(&pimu_w[tid * 16 + j]), hj, mu);
            lp = fmaf(__ldg(&piprec_w[tid * 16 + j]), hj, lp);
        }
        float prec = expf(lp) + 0.01f;
        float var  = 1.f / (1.f + prec);
        float stdv = sqrtf(var);
        sh_mu[tid]  = var * prec * mu;
        sh_std[tid] = stdv;
        float ls = logf(stdv);
#pragma unroll
        for (int o = 8; o; o >>= 1) ls += __shfl_down_sync(0x0000ffffu, ls, o);
        if (tid == 0) sh_logstd_sum = ls;
    }
    __syncthreads();

    // ---- t_part for compacted m rows ----
    if (tid < 128) {
        int i = tid >> 4, j = tid & 15;
        if (i < sh_mv) {
            int m = sh_midx[i];
            float a = 0.f;
#pragma unroll
            for (int t = 0; t < 16; t++) a = fmaf(sh_theta[m][t], sh_e1w[j][t], a);
            sh_tpart[i][j] = a;
        }
    }
    __syncthreads();

    // ---- main: one thread per (s,k) ----
    const int s = tid >> 6, k = tid & 63;
    const float* ep = eps + ((size_t)((s * K_ + k) * B_ + b)) * Z_;

    // zp = W_z @ z + e1_b, accumulated in regs then evicted to shared
    float eps2 = 0.f, z2s = 0.f;
    {
        float zp[16];
#pragma unroll
        for (int h = 0; h < 16; h++) zp[h] = sh_e1b[h];
        const float4* e4 = (const float4*)ep;
#pragma unroll
        for (int q = 0; q < 4; q++) {
            float4 v = __ldg(&e4[q]);
            float z0 = fmaf(sh_std[4*q+0], v.x, sh_mu[4*q+0]);
            float z1 = fmaf(sh_std[4*q+1], v.y, sh_mu[4*q+1]);
            float z2 = fmaf(sh_std[4*q+2], v.z, sh_mu[4*q+2]);
            float z3 = fmaf(sh_std[4*q+3], v.w, sh_mu[4*q+3]);
            eps2 = fmaf(v.x, v.x, eps2); eps2 = fmaf(v.y, v.y, eps2);
            eps2 = fmaf(v.z, v.z, eps2); eps2 = fmaf(v.w, v.w, eps2);
            z2s = fmaf(z0, z0, z2s); z2s = fmaf(z1, z1, z2s);
            z2s = fmaf(z2, z2, z2s); z2s = fmaf(z3, z3, z2s);
#pragma unroll 4
            for (int h = 0; h < 16; h++) {
                const float4 w = *(const float4*)&sh_e1w[h][16 + 4*q];
                float a = zp[h];
                a = fmaf(w.x, z0, a);
                a = fmaf(w.y, z1, a);
                a = fmaf(w.z, z2, a);
                a = fmaf(w.w, z3, a);
                zp[h] = a;
            }
        }
#pragma unroll
        for (int h = 0; h < 16; h++) sh_zp[tid][h] = zp[h];
    }
    const float pi_lp = -0.5f * eps2 - sh_logstd_sum - 8.f * LOG2PI;
    const float prior = -0.5f * z2s - 8.f * LOG2PI;

    // ---- energy: m-rows in groups of up to 4 sharing one pipelined weight pass ----
    const int mv = sh_mv;
    float energy = (float)mv * sh_e3b0;
    {
        const float* zp_sh = sh_zp[tid];
        int c0 = mv < 4 ? mv : 4;
        if (c0 > 0) energy += energy_dispatch(0, c0, zp_sh, sh_tpart, sh_e2w, sh_e2b, sh_e3w);
        if (mv > 4) energy += energy_dispatch(4, mv - 4, zp_sh, sh_tpart, sh_e2w, sh_e2b, sh_e3w);
    }

    float liw = prior - energy - pi_lp;
    float u = __ldg(&gumbel[(b * S_ + s) * K_ + k]);
    float gum = -logf(-logf(u + 1e-20f) + 1e-20f);

    sh_logiw[tid]  = liw;
    sh_logits[tid] = liw + gum;
    sh_energy[tid] = energy;
    __syncthreads();

    // ---- per-s reduction: argmax(logits), logsumexp(log_iws) ----
    const int warp = tid >> 5, lane = tid & 31;
    if (warp < S_) {
        const int ss = warp;
        const float* L = &sh_logits[ss * 64];
        float v0 = L[lane], v1 = L[lane + 32];
        float bv; int bi;
        if (v0 >= v1) { bv = v0; bi = lane; } else { bv = v1; bi = lane + 32; }
#pragma unroll
        for (int o = 16; o; o >>= 1) {
            float ov = __shfl_down_sync(0xffffffffu, bv, o);
            int   oi = __shfl_down_sync(0xffffffffu, bi, o);
            if (ov > bv || (ov == bv && oi < bi)) { bv = ov; bi = oi; }
        }
        int kstar = __shfl_sync(0xffffffffu, bi, 0);

        const float* LW = &sh_logiw[ss * 64];
        float l0 = LW[lane], l1 = LW[lane + 32];
        float mx = fmaxf(l0, l1);
#pragma unroll
        for (int o = 16; o; o >>= 1) mx = fmaxf(mx, __shfl_down_sync(0xffffffffu, mx, o));
        mx = __shfl_sync(0xffffffffu, mx, 0);
        float se = expf(l0 - mx) + expf(l1 - mx);
#pragma unroll
        for (int o = 16; o; o >>= 1) se += __shfl_down_sync(0xffffffffu, se, o);

        if (lane == 0) {
            float lse  = mx + logf(se);
            float lavg = lse - logf((float)K_);
            float ez   = sh_energy[ss * 64 + kstar];
            out[B_ * S_ * Z_ + b * S_ + ss] = -ez - lavg;
        }
        if (lane < 16) {
            float e = __ldg(&eps[((size_t)((ss * K_ + kstar) * B_ + b)) * Z_ + lane]);
            out[(b * S_ + ss) * Z_ + lane] = fmaf(sh_std[lane], e, sh_mu[lane]);
        }
    }
}

extern "C" void kernel_launch(void* const* d_in, const int* in_sizes, int n_in,
                              void* d_out, int out_size) {
    const float* thetas   = (const float*)d_in[0];
    const void*  nan_mask = d_in[1];
    const float* eps      = (const float*)d_in[2];
    const float* gumbel   = (const float*)d_in[3];
    int base = (n_in >= 17 && in_sizes[4] == 1) ? 5 : 4;
    const float* pi1_w    = (const float*)d_in[base + 0];
    const float* pi1_b    = (const float*)d_in[base + 1];
    const float* pimu_w   = (const float*)d_in[base + 2];
    const float* pimu_b   = (const float*)d_in[base + 3];
    const float* piprec_w = (const float*)d_in[base + 4];
    const float* piprec_b = (const float*)d_in[base + 5];
    const float* e1_w     = (const float*)d_in[base + 6];
    const float* e1_b     = (const float*)d_in[base + 7];
    const float* e2_w     = (const float*)d_in[base + 8];
    const float* e2_b     = (const float*)d_in[base + 9];
    const float* e3_w     = (const float*)d_in[base + 10];
    const float* e3_b     = (const float*)d_in[base + 11];

    ebm_kernel<<<B_, 256>>>(thetas, nan_mask, eps, gumbel,
                            pi1_w, pi1_b, pimu_w, pimu_b, piprec_w, piprec_b,
                            e1_w, e1_b, e2_w, e2_b, e3_w, e3_b,
                            (float*)d_out);
}

// round 16
// speedup vs baseline: 1.1215x; 1.1215x over previous
#include <cuda_runtime.h>

namespace {
constexpr int B_ = 512, M_ = 8, S_ = 4, K_ = 64, TH_ = 16, Z_ = 16, H_ = 16;
constexpr float LOG2PI = 1.8378770664093453f;
}

// Energy for CNT compacted m-rows sharing one weight pass.
template <int CNT>
__device__ __forceinline__ float energy_group(
    int base, const float* __restrict__ zp,
    const float (*__restrict__ tpart)[16],
    const float (*__restrict__ e2w)[16],
    const float2* __restrict__ e2c)      // (e2b[g], e3w[g]) packed
{
    float h1[CNT][16];
#pragma unroll
    for (int i = 0; i < CNT; i++) {
        const float4* tp = (const float4*)tpart[base + i];
#pragma unroll
        for (int q = 0; q < 4; q++) {
            float4 t = tp[q];
            h1[i][4*q+0] = fmaxf(t.x + zp[4*q+0], 0.f);
            h1[i][4*q+1] = fmaxf(t.y + zp[4*q+1], 0.f);
            h1[i][4*q+2] = fmaxf(t.z + zp[4*q+2], 0.f);
            h1[i][4*q+3] = fmaxf(t.w + zp[4*q+3], 0.f);
        }
    }
    float energy = 0.f;
    // unroll 1: exactly one g-row of weight loads in flight (anti-spill)
#pragma unroll 1
    for (int g = 0; g < 16; g++) {
        float2 c = e2c[g];          // (bias, e3w) in one LDS.64
        float acc[CNT];
#pragma unroll
        for (int i = 0; i < CNT; i++) acc[i] = c.x;
        const float4* wr = (const float4*)e2w[g];
#pragma unroll
        for (int q = 0; q < 4; q++) {
            float4 w = wr[q];   // warp-uniform broadcast, reused CNT times
#pragma unroll
            for (int i = 0; i < CNT; i++) {
                acc[i] = fmaf(w.x, h1[i][4*q+0], acc[i]);
                acc[i] = fmaf(w.y, h1[i][4*q+1], acc[i]);
                acc[i] = fmaf(w.z, h1[i][4*q+2], acc[i]);
                acc[i] = fmaf(w.w, h1[i][4*q+3], acc[i]);
            }
        }
        float rsum = fmaxf(acc[0], 0.f);
#pragma unroll
        for (int i = 1; i < CNT; i++) rsum += fmaxf(acc[i], 0.f);
        energy = fmaf(c.y, rsum, energy);
    }
    return energy;
}

__device__ __forceinline__ float energy_dispatch(
    int base, int cnt, const float* zp,
    const float (*tpart)[16], const float (*e2w)[16],
    const float2* e2c)
{
    switch (cnt) {
        case 1: return energy_group<1>(base, zp, tpart, e2w, e2c);
        case 2: return energy_group<2>(base, zp, tpart, e2w, e2c);
        case 3: return energy_group<3>(base, zp, tpart, e2w, e2c);
        default: return energy_group<4>(base, zp, tpart, e2w, e2c);
    }
}

__global__ void __launch_bounds__(256, 2) ebm_kernel(
    const float* __restrict__ thetas,
    const void*  __restrict__ nan_mask,
    const float* __restrict__ eps,
    const float* __restrict__ gumbel,
    const float* __restrict__ pi1_w,   const float* __restrict__ pi1_b,
    const float* __restrict__ pimu_w,  const float* __restrict__ pimu_b,
    const float* __restrict__ piprec_w,const float* __restrict__ piprec_b,
    const float* __restrict__ e1_w,    const float* __restrict__ e1_b,
    const float* __restrict__ e2_w,    const float* __restrict__ e2_b,
    const float* __restrict__ e3_w,    const float* __restrict__ e3_b,
    float* __restrict__ out)
{
    const int b = blockIdx.x;
    const int tid = threadIdx.x;

    __shared__ __align__(16) float sh_theta[M_][TH_];
    __shared__ __align__(16) float sh_e1w[H_][TH_ + Z_];   // [h][0:16]=W_t, [h][16:32]=W_z
    __shared__ __align__(16) float sh_e2w[H_][H_];
    __shared__ __align__(16) float sh_tpart[M_][H_];       // compacted valid m
    __shared__ __align__(8)  float2 sh_e2c[H_];            // (e2b, e3w) packed
    __shared__ float sh_e1b[H_];
    __shared__ float sh_mu[Z_], sh_std[Z_];
    __shared__ float sh_tsum[TH_], sh_h[H_];
    __shared__ float sh_logstd_sum, sh_e3b0;
    __shared__ int   sh_mv, sh_midx[M_];
    __shared__ float sh_logits[S_ * K_], sh_logiw[S_ * K_], sh_energy[S_ * K_];

    // ---- cooperative loads ----
    if (tid < 128) ((float*)sh_theta)[tid] = thetas[b * 128 + tid];
    ((float*)sh_e1w)[tid]       = e1_w[tid];
    ((float*)sh_e1w)[tid + 256] = e1_w[tid + 256];
    ((float*)sh_e2w)[tid]       = e2_w[tid];
    if (tid < 16) {
        sh_e1b[tid] = e1_b[tid];
        sh_e2c[tid] = make_float2(e2_b[tid], e3_w[tid]);
    }
    if (tid == 16) sh_e3b0 = e3_b[0];

    // ---- inline mask-dtype detection (reads only the 4096 guaranteed bytes) ----
    unsigned int myf = 0;
    {
        const uint4* w4 = (const uint4*)nan_mask;
        uint4 v = __ldg(&w4[tid]);
        unsigned int xs[4] = {v.x, v.y, v.z, v.w};
#pragma unroll
        for (int q = 0; q < 4; q++) {
            unsigned int x = xs[q];
            if (x != 0u && x != 0x3F800000u) myf |= 1u;
            if (x == 0x3F800000u) myf |= 2u;
            if (x & 0xFFFFFF00u) myf |= 4u;
        }
    }
    const unsigned int flags = (unsigned int)__syncthreads_or((int)myf);
    const int mode = (!(flags & 1u) && (flags & 2u)) ? 2 : ((flags & 4u) ? 1 : 0);

    // ---- per-b head prep ----
    if (tid < 16) {
        float s = 0.f;
#pragma unroll
        for (int m = 0; m < M_; m++) s += sh_theta[m][tid];
        sh_tsum[tid] = s;
    }
    if (tid == 17) {
        int mv = 0;
#pragma unroll
        for (int m = 0; m < M_; m++) {
            bool masked;
            if (mode == 1)      masked = ((const unsigned char*)nan_mask)[b * M_ + m] != 0;
            else if (mode == 2) masked = ((const float*)nan_mask)[b * M_ + m] != 0.f;
            else                masked = ((const int*)nan_mask)[b * M_ + m] != 0;
            if (!masked) sh_midx[mv++] = m;
        }
        sh_mv = mv;
    }
    __syncthreads();
    if (tid < 16) {
        float a = __ldg(&pi1_b[tid]);
#pragma unroll
        for (int t = 0; t < 16; t++) a = fmaf(__ldg(&pi1_w[tid * 16 + t]), sh_tsum[t], a);
        sh_h[tid] = fmaxf(a, 0.f);
    }
    __syncthreads();
    if (tid < 16) {
        float mu = __ldg(&pimu_b[tid]), lp = __ldg(&piprec_b[tid]);
#pragma unroll
        for (int j = 0; j < 16; j++) {
            float hj = sh_h[j];
            mu = fmaf(__ldg(&pimu_w[tid * 16 + j]), hj, mu);
            lp = fmaf(__ldg(&piprec_w[tid * 16 + j]), hj, lp);
        }
        float prec = expf(lp) + 0.01f;
        float var  = 1.f / (1.f + prec);
        float stdv = sqrtf(var);
        sh_mu[tid]  = var * prec * mu;
        sh_std[tid] = stdv;
        float ls = logf(stdv);
#pragma unroll
        for (int o = 8; o; o >>= 1) ls += __shfl_down_sync(0x0000ffffu, ls, o);
        if (tid == 0) sh_logstd_sum = ls;
    }
    __syncthreads();

    // ---- t_part for compacted m rows ----
    if (tid < 128) {
        int i = tid >> 4, j = tid & 15;
        if (i < sh_mv) {
            int m = sh_midx[i];
            float a = 0.f;
#pragma unroll
            for (int t = 0; t < 16; t++) a = fmaf(sh_theta[m][t], sh_e1w[j][t], a);
            sh_tpart[i][j] = a;
        }
    }
    __syncthreads();

    // ---- main: one thread per (s,k) ----
    const int s = tid >> 6, k = tid & 63;
    const float* ep = eps + ((size_t)((s * K_ + k) * B_ + b)) * Z_;

    // zp = W_z @ z + e1_b, accumulated while streaming eps
    float zp[16];
#pragma unroll
    for (int h = 0; h < 16; h++) zp[h] = sh_e1b[h];
    float eps2 = 0.f, z2s = 0.f;
    {
        const float4* e4 = (const float4*)ep;
#pragma unroll
        for (int q = 0; q < 4; q++) {
            float4 v = __ldg(&e4[q]);
            float z0 = fmaf(sh_std[4*q+0], v.x, sh_mu[4*q+0]);
            float z1 = fmaf(sh_std[4*q+1], v.y, sh_mu[4*q+1]);
            float z2 = fmaf(sh_std[4*q+2], v.z, sh_mu[4*q+2]);
            float z3 = fmaf(sh_std[4*q+3], v.w, sh_mu[4*q+3]);
            eps2 = fmaf(v.x, v.x, eps2); eps2 = fmaf(v.y, v.y, eps2);
            eps2 = fmaf(v.z, v.z, eps2); eps2 = fmaf(v.w, v.w, eps2);
            z2s = fmaf(z0, z0, z2s); z2s = fmaf(z1, z1, z2s);
            z2s = fmaf(z2, z2, z2s); z2s = fmaf(z3, z3, z2s);
#pragma unroll 4
            for (int h = 0; h < 16; h++) {
                const float4 w = *(const float4*)&sh_e1w[h][16 + 4*q];
                float a = zp[h];
                a = fmaf(w.x, z0, a);
                a = fmaf(w.y, z1, a);
                a = fmaf(w.z, z2, a);
                a = fmaf(w.w, z3, a);
                zp[h] = a;
            }
        }
    }
    const float pi_lp = -0.5f * eps2 - sh_logstd_sum - 8.f * LOG2PI;
    const float prior = -0.5f * z2s - 8.f * LOG2PI;

    // ---- energy: m-rows in groups of up to 4 sharing one weight pass ----
    const int mv = sh_mv;
    float energy = (float)mv * sh_e3b0;
    {
        int c0 = mv < 4 ? mv : 4;
        if (c0 > 0) energy += energy_dispatch(0, c0, zp, sh_tpart, sh_e2w, sh_e2c);
        if (mv > 4) energy += energy_dispatch(4, mv - 4, zp, sh_tpart, sh_e2w, sh_e2c);
    }

    float liw = prior - energy - pi_lp;
    float u = __ldg(&gumbel[(b * S_ + s) * K_ + k]);
    // fast logs: gumbel noise only affects argmax tie-breaking, 2-ulp error is safe
    float gum = -__logf(-__logf(u + 1e-20f) + 1e-20f);

    sh_logiw[tid]  = liw;
    sh_logits[tid] = liw + gum;
    sh_energy[tid] = energy;
    __syncthreads();

    // ---- per-s reduction: argmax(logits), logsumexp(log_iws) ----
    const int warp = tid >> 5, lane = tid & 31;
    if (warp < S_) {
        const int ss = warp;
        const float* L = &sh_logits[ss * 64];
        float v0 = L[lane], v1 = L[lane + 32];
        float bv; int bi;
        if (v0 >= v1) { bv = v0; bi = lane; } else { bv = v1; bi = lane + 32; }
#pragma unroll
        for (int o = 16; o; o >>= 1) {
            float ov = __shfl_down_sync(0xffffffffu, bv, o);
            int   oi = __shfl_down_sync(0xffffffffu, bi, o);
            if (ov > bv || (ov == bv && oi < bi)) { bv = ov; bi = oi; }
        }
        int kstar = __shfl_sync(0xffffffffu, bi, 0);

        const float* LW = &sh_logiw[ss * 64];
        float l0 = LW[lane], l1 = LW[lane + 32];
        float mx = fmaxf(l0, l1);
#pragma unroll
        for (int o = 16; o; o >>= 1) mx = fmaxf(mx, __shfl_down_sync(0xffffffffu, mx, o));
        mx = __shfl_sync(0xffffffffu, mx, 0);
        float se = expf(l0 - mx) + expf(l1 - mx);
#pragma unroll
        for (int o = 16; o; o >>= 1) se += __shfl_down_sync(0xffffffffu, se, o);

        if (lane == 0) {
            float lse  = mx + logf(se);
            float lavg = lse - logf((float)K_);
            float ez   = sh_energy[ss * 64 + kstar];
            out[B_ * S_ * Z_ + b * S_ + ss] = -ez - lavg;
        }
        if (lane < 16) {
            float e = __ldg(&eps[((size_t)((ss * K_ + kstar) * B_ + b)) * Z_ + lane]);
            out[(b * S_ + ss) * Z_ + lane] = fmaf(sh_std[lane], e, sh_mu[lane]);
        }
    }
}

extern "C" void kernel_launch(void* const* d_in, const int* in_sizes, int n_in,
                              void* d_out, int out_size) {
    const float* thetas   = (const float*)d_in[0];
    const void*  nan_mask = d_in[1];
    const float* eps      = (const float*)d_in[2];
    const float* gumbel   = (const float*)d_in[3];
    int base = (n_in >= 17 && in_sizes[4] == 1) ? 5 : 4;
    const float* pi1_w    = (const float*)d_in[base + 0];
    const float* pi1_b    = (const float*)d_in[base + 1];
    const float* pimu_w   = (const float*)d_in[base + 2];
    const float* pimu_b   = (const float*)d_in[base + 3];
    const float* piprec_w = (const float*)d_in[base + 4];
    const float* piprec_b = (const float*)d_in[base + 5];
    const float* e1_w     = (const float*)d_in[base + 6];
    const float* e1_b     = (const float*)d_in[base + 7];
    const float* e2_w     = (const float*)d_in[base + 8];
    const float* e2_b     = (const float*)d_in[base + 9];
    const float* e3_w     = (const float*)d_in[base + 10];
    const float* e3_b     = (const float*)d_in[base + 11];

    ebm_kernel<<<B_, 256>>>(thetas, nan_mask, eps, gumbel,
                            pi1_w, pi1_b, pimu_w, pimu_b, piprec_w, piprec_b,
                            e1_w, e1_b, e2_w, e2_b, e3_w, e3_b,
                            (float*)d_out);
}

// round 17
// speedup vs baseline: 1.1334x; 1.0106x over previous
#include <cuda_runtime.h>

namespace {
constexpr int B_ = 512, M_ = 8, S_ = 4, K_ = 64, TH_ = 16, Z_ = 16, H_ = 16;
constexpr float LOG2PI = 1.8378770664093453f;
}

// ---- packed f32x2 helpers ----
__device__ __forceinline__ unsigned long long pk2(float lo, float hi) {
    unsigned long long r;
    asm("mov.b64 %0, {%1, %2};" : "=l"(r) : "f"(lo), "f"(hi));
    return r;
}
__device__ __forceinline__ void upk2(unsigned long long v, float& lo, float& hi) {
    asm("mov.b64 {%0, %1}, %2;" : "=f"(lo), "=f"(hi) : "l"(v));
}
__device__ __forceinline__ unsigned long long fma2(unsigned long long a,
                                                   unsigned long long b,
                                                   unsigned long long c) {
    unsigned long long d;
    asm("fma.rn.f32x2 %0, %1, %2, %3;" : "=l"(d) : "l"(a), "l"(b), "l"(c));
    return d;
}
__device__ __forceinline__ unsigned long long add2(unsigned long long a,
                                                   unsigned long long b) {
    unsigned long long d;
    asm("add.rn.f32x2 %0, %1, %2;" : "=l"(d) : "l"(a), "l"(b));
    return d;
}
__device__ __forceinline__ unsigned long long relu2(unsigned long long x) {
    float a, bb; upk2(x, a, bb);
    return pk2(fmaxf(a, 0.f), fmaxf(bb, 0.f));
}

// Energy for CNT compacted m-rows sharing one weight pass; packed f32x2 math.
// Weights are reinterpreted in place (float4 row bytes == ulonglong2 pair bytes).
template <int CNT>
__device__ __forceinline__ float energy_group(
    int base, const unsigned long long* __restrict__ zp2,  // packed zp, 8 pairs
    const float (*__restrict__ tpart)[16],
    const float (*__restrict__ e2w)[16],
    const float2* __restrict__ e2c)      // (e2b[g], e3w[g]) packed
{
    unsigned long long h1p[CNT][8];
#pragma unroll
    for (int i = 0; i < CNT; i++) {
        const ulonglong2* tp2 = (const ulonglong2*)tpart[base + i];
#pragma unroll
        for (int q = 0; q < 4; q++) {
            ulonglong2 t = tp2[q];
            h1p[i][2*q+0] = relu2(add2(t.x, zp2[2*q+0]));
            h1p[i][2*q+1] = relu2(add2(t.y, zp2[2*q+1]));
        }
    }
    float energy = 0.f;
    // unroll 1: one g-row of weight loads in flight (anti-spill)
#pragma unroll 1
    for (int g = 0; g < 16; g++) {
        float2 c = e2c[g];
        unsigned long long acc2[CNT];
#pragma unroll
        for (int i = 0; i < CNT; i++) acc2[i] = pk2(c.x, 0.f);
        const ulonglong2* wr2 = (const ulonglong2*)e2w[g];
#pragma unroll
        for (int q = 0; q < 4; q++) {
            ulonglong2 w = wr2[q];   // warp-uniform broadcast; pairs pre-packed
#pragma unroll
            for (int i = 0; i < CNT; i++) {
                acc2[i] = fma2(w.x, h1p[i][2*q+0], acc2[i]);
                acc2[i] = fma2(w.y, h1p[i][2*q+1], acc2[i]);
            }
        }
        float rsum = 0.f;
#pragma unroll
        for (int i = 0; i < CNT; i++) {
            float lo, hi; upk2(acc2[i], lo, hi);
            rsum += fmaxf(lo + hi, 0.f);
        }
        energy = fmaf(c.y, rsum, energy);
    }
    return energy;
}

__device__ __forceinline__ float energy_dispatch(
    int base, int cnt, const unsigned long long* zp2,
    const float (*tpart)[16], const float (*e2w)[16],
    const float2* e2c)
{
    switch (cnt) {
        case 1: return energy_group<1>(base, zp2, tpart, e2w, e2c);
        case 2: return energy_group<2>(base, zp2, tpart, e2w, e2c);
        case 3: return energy_group<3>(base, zp2, tpart, e2w, e2c);
        default: return energy_group<4>(base, zp2, tpart, e2w, e2c);
    }
}

__global__ void __launch_bounds__(256, 2) ebm_kernel(
    const float* __restrict__ thetas,
    const void*  __restrict__ nan_mask,
    const float* __restrict__ eps,
    const float* __restrict__ gumbel,
    const float* __restrict__ pi1_w,   const float* __restrict__ pi1_b,
    const float* __restrict__ pimu_w,  const float* __restrict__ pimu_b,
    const float* __restrict__ piprec_w,const float* __restrict__ piprec_b,
    const float* __restrict__ e1_w,    const float* __restrict__ e1_b,
    const float* __restrict__ e2_w,    const float* __restrict__ e2_b,
    const float* __restrict__ e3_w,    const float* __restrict__ e3_b,
    float* __restrict__ out)
{
    const int b = blockIdx.x;
    const int tid = threadIdx.x;

    __shared__ __align__(16) float sh_theta[M_][TH_];
    __shared__ __align__(16) float sh_e1w[H_][TH_ + Z_];   // [h][0:16]=W_t, [h][16:32]=W_z
    __shared__ __align__(16) float sh_e2w[H_][H_];
    __shared__ __align__(16) float sh_tpart[M_][H_];       // compacted valid m
    __shared__ __align__(8)  float2 sh_e2c[H_];            // (e2b, e3w) packed
    __shared__ float sh_e1b[H_];
    __shared__ float sh_mu[Z_], sh_std[Z_];
    __shared__ float sh_tsum[TH_], sh_h[H_];
    __shared__ float sh_logstd_sum, sh_e3b0;
    __shared__ int   sh_mv, sh_midx[M_];
    __shared__ float sh_logits[S_ * K_], sh_logiw[S_ * K_], sh_energy[S_ * K_];

    // ---- cooperative loads ----
    if (tid < 128) ((float*)sh_theta)[tid] = thetas[b * 128 + tid];
    ((float*)sh_e1w)[tid]       = e1_w[tid];
    ((float*)sh_e1w)[tid + 256] = e1_w[tid + 256];
    ((float*)sh_e2w)[tid]       = e2_w[tid];
    if (tid < 16) {
        sh_e1b[tid] = e1_b[tid];
        sh_e2c[tid] = make_float2(e2_b[tid], e3_w[tid]);
    }
    if (tid == 16) sh_e3b0 = e3_b[0];

    // ---- inline mask-dtype detection (reads only the 4096 guaranteed bytes) ----
    unsigned int myf = 0;
    {
        const uint4* w4 = (const uint4*)nan_mask;
        uint4 v = __ldg(&w4[tid]);
        unsigned int xs[4] = {v.x, v.y, v.z, v.w};
#pragma unroll
        for (int q = 0; q < 4; q++) {
            unsigned int x = xs[q];
            if (x != 0u && x != 0x3F800000u) myf |= 1u;
            if (x == 0x3F800000u) myf |= 2u;
            if (x & 0xFFFFFF00u) myf |= 4u;
        }
    }
    const unsigned int flags = (unsigned int)__syncthreads_or((int)myf);
    const int mode = (!(flags & 1u) && (flags & 2u)) ? 2 : ((flags & 4u) ? 1 : 0);

    // ---- per-b head prep ----
    if (tid < 16) {
        float s = 0.f;
#pragma unroll
        for (int m = 0; m < M_; m++) s += sh_theta[m][tid];
        sh_tsum[tid] = s;
    }
    if (tid == 17) {
        int mv = 0;
#pragma unroll
        for (int m = 0; m < M_; m++) {
            bool masked;
            if (mode == 1)      masked = ((const unsigned char*)nan_mask)[b * M_ + m] != 0;
            else if (mode == 2) masked = ((const float*)nan_mask)[b * M_ + m] != 0.f;
            else                masked = ((const int*)nan_mask)[b * M_ + m] != 0;
            if (!masked) sh_midx[mv++] = m;
        }
        sh_mv = mv;
    }
    __syncthreads();
    if (tid < 16) {
        float a = __ldg(&pi1_b[tid]);
#pragma unroll
        for (int t = 0; t < 16; t++) a = fmaf(__ldg(&pi1_w[tid * 16 + t]), sh_tsum[t], a);
        sh_h[tid] = fmaxf(a, 0.f);
    }
    __syncthreads();
    if (tid < 16) {
        float mu = __ldg(&pimu_b[tid]), lp = __ldg(&piprec_b[tid]);
#pragma unroll
        for (int j = 0; j < 16; j++) {
            float hj = sh_h[j];
            mu = fmaf(__ldg(&pimu_w[tid * 16 + j]), hj, mu);
            lp = fmaf(__ldg(&piprec_w[tid * 16 + j]), hj, lp);
        }
        float prec = expf(lp) + 0.01f;
        float var  = 1.f / (1.f + prec);
        float stdv = sqrtf(var);
        sh_mu[tid]  = var * prec * mu;
        sh_std[tid] = stdv;
        float ls = logf(stdv);
#pragma unroll
        for (int o = 8; o; o >>= 1) ls += __shfl_down_sync(0x0000ffffu, ls, o);
        if (tid == 0) sh_logstd_sum = ls;
    }
    __syncthreads();

    // ---- t_part for compacted m rows ----
    if (tid < 128) {
        int i = tid >> 4, j = tid & 15;
        if (i < sh_mv) {
            int m = sh_midx[i];
            float a = 0.f;
#pragma unroll
            for (int t = 0; t < 16; t++) a = fmaf(sh_theta[m][t], sh_e1w[j][t], a);
            sh_tpart[i][j] = a;
        }
    }
    __syncthreads();

    // ---- main: one thread per (s,k) ----
    const int s = tid >> 6, k = tid & 63;
    const float* ep = eps + ((size_t)((s * K_ + k) * B_ + b)) * Z_;

    // zp = W_z @ z + e1_b, scalar accumulation (proven structure)
    float zp[16];
#pragma unroll
    for (int h = 0; h < 16; h++) zp[h] = sh_e1b[h];
    float eps2 = 0.f, z2s = 0.f;
    {
        const float4* e4 = (const float4*)ep;
#pragma unroll
        for (int q = 0; q < 4; q++) {
            float4 v = __ldg(&e4[q]);
            float z0 = fmaf(sh_std[4*q+0], v.x, sh_mu[4*q+0]);
            float z1 = fmaf(sh_std[4*q+1], v.y, sh_mu[4*q+1]);
            float z2 = fmaf(sh_std[4*q+2], v.z, sh_mu[4*q+2]);
            float z3 = fmaf(sh_std[4*q+3], v.w, sh_mu[4*q+3]);
            eps2 = fmaf(v.x, v.x, eps2); eps2 = fmaf(v.y, v.y, eps2);
            eps2 = fmaf(v.z, v.z, eps2); eps2 = fmaf(v.w, v.w, eps2);
            z2s = fmaf(z0, z0, z2s); z2s = fmaf(z1, z1, z2s);
            z2s = fmaf(z2, z2, z2s); z2s = fmaf(z3, z3, z2s);
#pragma unroll 4
            for (int h = 0; h < 16; h++) {
                const float4 w = *(const float4*)&sh_e1w[h][16 + 4*q];
                float a = zp[h];
                a = fmaf(w.x, z0, a);
                a = fmaf(w.y, z1, a);
                a = fmaf(w.z, z2, a);
                a = fmaf(w.w, z3, a);
                zp[h] = a;
            }
        }
    }
    const float pi_lp = -0.5f * eps2 - sh_logstd_sum - 8.f * LOG2PI;
    const float prior = -0.5f * z2s - 8.f * LOG2PI;

    // pack zp once (scalar zp dies here)
    unsigned long long zp2[8];
#pragma unroll
    for (int p = 0; p < 8; p++) zp2[p] = pk2(zp[2*p], zp[2*p+1]);

    // ---- energy: m-rows in groups of up to 4, packed f32x2 weight pass ----
    const int mv = sh_mv;
    float energy = (float)mv * sh_e3b0;
    {
        int c0 = mv < 4 ? mv : 4;
        if (c0 > 0) energy += energy_dispatch(0, c0, zp2, sh_tpart, sh_e2w, sh_e2c);
        if (mv > 4) energy += energy_dispatch(4, mv - 4, zp2, sh_tpart, sh_e2w, sh_e2c);
    }

    float liw = prior - energy - pi_lp;
    float u = __ldg(&gumbel[(b * S_ + s) * K_ + k]);
    // fast logs: gumbel noise only affects argmax tie-breaking
    float gum = -__logf(-__logf(u + 1e-20f) + 1e-20f);

    sh_logiw[tid]  = liw;
    sh_logits[tid] = liw + gum;
    sh_energy[tid] = energy;
    __syncthreads();

    // ---- per-s reduction: argmax(logits), logsumexp(log_iws) ----
    const int warp = tid >> 5, lane = tid & 31;
    if (warp < S_) {
        const int ss = warp;
        const float* L = &sh_logits[ss * 64];
        float v0 = L[lane], v1 = L[lane + 32];
        float bv; int bi;
        if (v0 >= v1) { bv = v0; bi = lane; } else { bv = v1; bi = lane + 32; }
#pragma unroll
        for (int o = 16; o; o >>= 1) {
            float ov = __shfl_down_sync(0xffffffffu, bv, o);
            int   oi = __shfl_down_sync(0xffffffffu, bi, o);
            if (ov > bv || (ov == bv && oi < bi)) { bv = ov; bi = oi; }
        }
        int kstar = __shfl_sync(0xffffffffu, bi, 0);

        const float* LW = &sh_logiw[ss * 64];
        float l0 = LW[lane], l1 = LW[lane + 32];
        float mx = fmaxf(l0, l1);
#pragma unroll
        for (int o = 16; o; o >>= 1) mx = fmaxf(mx, __shfl_down_sync(0xffffffffu, mx, o));
        mx = __shfl_sync(0xffffffffu, mx, 0);
        float se = expf(l0 - mx) + expf(l1 - mx);
#pragma unroll
        for (int o = 16; o; o >>= 1) se += __shfl_down_sync(0xffffffffu, se, o);

        if (lane == 0) {
            float lse  = mx + logf(se);
            float lavg = lse - logf((float)K_);
            float ez   = sh_energy[ss * 64 + kstar];
            out[B_ * S_ * Z_ + b * S_ + ss] = -ez - lavg;
        }
        if (lane < 16) {
            float e = __ldg(&eps[((size_t)((ss * K_ + kstar) * B_ + b)) * Z_ + lane]);
            out[(b * S_ + ss) * Z_ + lane] = fmaf(sh_std[lane], e, sh_mu[lane]);
        }
    }
}

extern "C" void kernel_launch(void* const* d_in, const int* in_sizes, int n_in,
                              void* d_out, int out_size) {
    const float* thetas   = (const float*)d_in[0];
    const void*  nan_mask = d_in[1];
    const float* eps      = (const float*)d_in[2];
    const float* gumbel   = (const float*)d_in[3];
    int base = (n_in >= 17 && in_sizes[4] == 1) ? 5 : 4;
    const float* pi1_w    = (const float*)d_in[base + 0];
    const float* pi1_b    = (const float*)d_in[base + 1];
    const float* pimu_w   = (const float*)d_in[base + 2];
    const float* pimu_b   = (const float*)d_in[base + 3];
    const float* piprec_w = (const float*)d_in[base + 4];
    const float* piprec_b = (const float*)d_in[base + 5];
    const float* e1_w     = (const float*)d_in[base + 6];
    const float* e1_b     = (const float*)d_in[base + 7];
    const float* e2_w     = (const float*)d_in[base + 8];
    const float* e2_b     = (const float*)d_in[base + 9];
    const float* e3_w     = (const float*)d_in[base + 10];
    const float* e3_b     = (const float*)d_in[base + 11];

    ebm_kernel<<<B_, 256>>>(thetas, nan_mask, eps, gumbel,
                            pi1_w, pi1_b, pimu_w, pimu_b, piprec_w, piprec_b,
                            e1_w, e1_b, e2_w, e2_b, e3_w, e3_b,
                            (float*)d_out);
}